// round 10
// baseline (speedup 1.0000x reference)
#include <cuda_runtime.h>
#include <cuda_fp8.h>
#include <cstdint>
#include <cstddef>

#define K_DIM 1024
#define N_DIM 1024
#define NKB 32
#define LN2F 0.69314718246459960938f

#define BM 128
#define BN 128
#define BK 32                 // bytes per k-block (fp8) == one MX block
#define RSTRIDE 48            // bytes per smem row (32 data + 16 pad)
#define STG_BYTES (BM * RSTRIDE)
#define NSTG 5                // pipeline stages (prefetch distance 4)

// Exact e5m2 grid values stored AS fp8 + per-32-block scales (fp32, inexact jax)
__device__ __align__(16) uint8_t g_xv[(size_t)8 * 8192 * 1024];
__device__ __align__(16) uint8_t g_wv[(size_t)1024 * 1024];
__device__ __align__(16) float g_xs[(size_t)NKB * 65536];   // [kb][row]
__device__ __align__(16) float g_ws[(size_t)NKB * 1024];    // [kb][row]

// floor(logf(s)/ln2f) with exponent-bits fast path (bitwise-equal in fast region)
__device__ __forceinline__ int jax_floor_log2(float s) {
    uint32_t b = __float_as_uint(s);
    uint32_t mant = b & 0x7fffffu;
    int ef = (int)(b >> 23);
    if (ef == 0 || mant >= 0x7ff000u || (mant != 0u && mant <= 0x4000u))
        return (int)floorf(logf(s) / LN2F);
    return ef - 127;
}

// Literal jax block scale: expf((floor(log2(amax)) - 15) * ln2f)
__device__ __forceinline__ float jax_scale(float amax) {
    if (!(amax > 0.f)) return 1.f;
    int E = jax_floor_log2(amax);
    return expf((float)(E - 15) * LN2F);
}

// One thread = one 32-element MX block. Emits exact e5m2 grid values (fp8) + scale.
__global__ void quant_v(const float* __restrict__ x, uint8_t* __restrict__ qv,
                        float* __restrict__ qs, int nblk, int rows) {
    __shared__ float sStep[30];
    if (threadIdx.x < 30) sStep[threadIdx.x] = expf((float)((int)threadIdx.x - 16) * LN2F);
    __syncthreads();
    int b = blockIdx.x * blockDim.x + threadIdx.x;
    if (b >= nblk) return;
    const float4* p = reinterpret_cast<const float4*>(x) + (size_t)b * 8;
    float4 v[8];
    float amax = 0.f;
#pragma unroll
    for (int i = 0; i < 8; i++) {
        v[i] = p[i];
        amax = fmaxf(amax, fmaxf(fmaxf(fabsf(v[i].x), fabsf(v[i].y)),
                                 fmaxf(fabsf(v[i].z), fabsf(v[i].w))));
    }
    float scale = jax_scale(amax);
    const float* f = reinterpret_cast<const float*>(v);
    uint4 ov[2];                                   // 32 fp8 bytes
    uint8_t* o = reinterpret_cast<uint8_t*>(ov);
#pragma unroll
    for (int i = 0; i < 32; i++) {
        float t = f[i] / scale;            // true div: selection bitwise as ref
        float av = fabsf(t);
        float r = 0.f;
        if (av > 0.f) {
            float sat = fminf(av, 57344.f);
            int e = jax_floor_log2(sat);
            e = e < -14 ? -14 : e;
            float step = sStep[e + 14];    // bitwise == expf((e-2)*ln2f)
            float n = rintf(sat / step);   // true div: bitwise as ref
            r = copysignf(ldexpf(n, e - 2), t);   // EXACT e5m2 grid value
        }
        o[i] = __nv_cvt_float_to_fp8(r, __NV_SATFINITE, __NV_E5M2);  // exact
    }
    uint4* dst = reinterpret_cast<uint4*>(qv) + (size_t)b * 2;
    dst[0] = ov[0];
    dst[1] = ov[1];
    qs[(size_t)(b & 31) * rows + (b >> 5)] = scale;
}

__device__ __forceinline__ void cp_async16(uint32_t dst, const void* src) {
    asm volatile("cp.async.cg.shared.global [%0], [%1], 16;\n" :: "r"(dst), "l"(src));
}

__device__ __forceinline__ unsigned long long pk2(float lo, float hi) {
    unsigned long long r;
    asm("mov.b64 %0, {%1, %2};" : "=l"(r) : "f"(lo), "f"(hi));
    return r;
}
__device__ __forceinline__ float2 upk2(unsigned long long v) {
    float2 r;
    asm("mov.b64 {%0, %1}, %2;" : "=f"(r.x), "=f"(r.y) : "l"(v));
    return r;
}
__device__ __forceinline__ unsigned long long mul2(unsigned long long a,
                                                   unsigned long long b) {
    unsigned long long r;
    asm("mul.rn.f32x2 %0, %1, %2;" : "=l"(r) : "l"(a), "l"(b));
    return r;
}
__device__ __forceinline__ void fma2(unsigned long long& acc, unsigned long long a,
                                     unsigned long long b) {
    asm("fma.rn.f32x2 %0, %1, %2, %0;" : "+l"(acc) : "l"(a), "l"(b));
}

// 128x128 tile GEMM, 16 warps (warp tile 32x32), 5-stage cp.async pipeline
// (prefetch distance 4 hides 577-cyc DRAM), fp8-e5m2 m16n8k32 MMA with
// immediate packed-f32x2 scale fold; literal jax out-quant in epilogue.
__global__ __launch_bounds__(512) void gemm_qd(const float* __restrict__ bias,
                                               float* __restrict__ out, int mrows) {
    extern __shared__ uint8_t dynsm[];
    uint8_t* sA = dynsm;                       // [NSTG][STG_BYTES]
    uint8_t* sB = dynsm + NSTG * STG_BYTES;    // [NSTG][STG_BYTES]
    __shared__ float sSX[NSTG][BM];
    __shared__ float sSW[NSTG][BN];
    __shared__ float sBias[BN];
    __shared__ float sStep[30];

    const int tid = threadIdx.x;
    const int m0 = blockIdx.y * BM;
    const int n0 = blockIdx.x * BN;
    if (tid < 30) sStep[tid] = expf((float)(tid - 16) * LN2F);
    if (tid < BN) sBias[tid] = bias[n0 + tid];

    const int lane = tid & 31;
    const int warp = tid >> 5;          // 0..15
    const int wm = warp >> 2;           // 0..3  (32 rows)
    const int wn = warp & 3;            // 0..3  (32 cols = one quant block)

    uint32_t sAu[NSTG], sBu[NSTG], sSXu[NSTG], sSWu[NSTG];
#pragma unroll
    for (int s = 0; s < NSTG; s++) {
        sAu[s] = (uint32_t)__cvta_generic_to_shared(sA + s * STG_BYTES);
        sBu[s] = (uint32_t)__cvta_generic_to_shared(sB + s * STG_BYTES);
        sSXu[s] = (uint32_t)__cvta_generic_to_shared(&sSX[s][0]);
        sSWu[s] = (uint32_t)__cvta_generic_to_shared(&sSW[s][0]);
    }

    unsigned long long acc2[2][4][2];
#pragma unroll
    for (int i = 0; i < 2; i++)
#pragma unroll
        for (int j = 0; j < 4; j++)
#pragma unroll
            for (int h = 0; h < 2; h++) acc2[i][j][h] = 0ull;

    // 512 threads: tid<256 loads one 16B chunk of A, tid>=256 one of B.
    const int lrow = (tid & 255) >> 1, lch = tid & 1;
    auto load_stage = [&](int stage, int kt) {
        int k0 = kt * BK;
        if (tid < 256)
            cp_async16(sAu[stage] + (uint32_t)(lrow * RSTRIDE + lch * 16),
                       &g_xv[(size_t)(m0 + lrow) * K_DIM + k0 + lch * 16]);
        else
            cp_async16(sBu[stage] + (uint32_t)(lrow * RSTRIDE + lch * 16),
                       &g_wv[(size_t)(n0 + lrow) * K_DIM + k0 + lch * 16]);
        if (tid < 32)
            cp_async16(sSXu[stage] + tid * 16, &g_xs[(size_t)kt * mrows + m0 + tid * 4]);
        else if (tid < 64)
            cp_async16(sSWu[stage] + (tid - 32) * 16,
                       &g_ws[(size_t)kt * N_DIM + n0 + (tid - 32) * 4]);
        asm volatile("cp.async.commit_group;\n");
    };

    const int gid = lane >> 2, tig = lane & 3;
    const int NK = K_DIM / BK;   // 32

#pragma unroll
    for (int s = 0; s < 4; s++) load_stage(s, s);   // prefetch distance 4

    int st = 0;
    for (int kt = 0; kt < NK; kt++) {
        // Wait until stage st's group is complete (ladder at the tail).
        if (kt < NK - 3)      asm volatile("cp.async.wait_group 3;\n");
        else if (kt == NK - 3) asm volatile("cp.async.wait_group 2;\n");
        else if (kt == NK - 2) asm volatile("cp.async.wait_group 1;\n");
        else                   asm volatile("cp.async.wait_group 0;\n");
        __syncthreads();

        // Prefetch 4 ahead into the slot consumed last iteration.
        if (kt + 4 < NK) {
            int pf = st + 4 >= NSTG ? st - 1 : st + 4;
            load_stage(pf, kt + 4);
        }

        // Scales first (LDS latency hidden under LDSM/MMA).
        unsigned long long sxp[2][2], swp[4];
#pragma unroll
        for (int mf = 0; mf < 2; mf++) {
            float s0 = sSX[st][wm * 32 + mf * 16 + gid];
            float s1 = sSX[st][wm * 32 + mf * 16 + 8 + gid];
            sxp[mf][0] = pk2(s0, s0);
            sxp[mf][1] = pk2(s1, s1);
        }
#pragma unroll
        for (int nf = 0; nf < 4; nf++)
            swp[nf] = pk2(sSW[st][wn * 32 + nf * 8 + tig * 2],
                          sSW[st][wn * 32 + nf * 8 + tig * 2 + 1]);

        // A fragments: one x4 per m16 tile covers full k32 (32 bytes/row).
        uint32_t a[2][4];
#pragma unroll
        for (int mf = 0; mf < 2; mf++) {
            uint32_t addr = sAu[st] +
                (uint32_t)((wm * 32 + mf * 16 + (lane & 15)) * RSTRIDE +
                           (lane >> 4) * 16);
            asm volatile("ldmatrix.sync.aligned.m8n8.x4.shared.b16 {%0,%1,%2,%3}, [%4];\n"
                         : "=r"(a[mf][0]), "=r"(a[mf][1]), "=r"(a[mf][2]), "=r"(a[mf][3])
                         : "r"(addr));
        }
        // B fragments: one x4 per PAIR of n8 tiles.
        uint32_t b[4][2];
#pragma unroll
        for (int np = 0; np < 2; np++) {
            uint32_t addr = sBu[st] +
                (uint32_t)((wn * 32 + np * 16 + ((lane >> 4) & 1) * 8 + (lane & 7)) * RSTRIDE +
                           ((lane >> 3) & 1) * 16);
            asm volatile("ldmatrix.sync.aligned.m8n8.x4.shared.b16 {%0,%1,%2,%3}, [%4];\n"
                         : "=r"(b[np * 2][0]), "=r"(b[np * 2][1]),
                           "=r"(b[np * 2 + 1][0]), "=r"(b[np * 2 + 1][1])
                         : "r"(addr));
        }

        // MMA + immediate fold (c is a short-lived temp; order per accumulator
        // identical to previous rounds -> bitwise-same output).
#pragma unroll
        for (int mf = 0; mf < 2; mf++)
#pragma unroll
            for (int nf = 0; nf < 4; nf++) {
                float c0 = 0.f, c1 = 0.f, c2 = 0.f, c3 = 0.f;
                asm volatile(
                    "mma.sync.aligned.m16n8k32.row.col.f32.e5m2.e5m2.f32 "
                    "{%0,%1,%2,%3}, {%4,%5,%6,%7}, {%8,%9}, {%0,%1,%2,%3};\n"
                    : "+f"(c0), "+f"(c1), "+f"(c2), "+f"(c3)
                    : "r"(a[mf][0]), "r"(a[mf][1]), "r"(a[mf][2]), "r"(a[mf][3]),
                      "r"(b[nf][0]), "r"(b[nf][1]));
                fma2(acc2[mf][nf][0], pk2(c0, c1), mul2(sxp[mf][0], swp[nf]));
                fma2(acc2[mf][nf][1], pk2(c2, c3), mul2(sxp[mf][1], swp[nf]));
            }

        st = st + 1 >= NSTG ? 0 : st + 1;
    }

    // Epilogue: +bias, literal jax MX e5m2 quant-dequant over 32 consecutive n.
#pragma unroll
    for (int mf = 0; mf < 2; mf++) {
#pragma unroll
        for (int h = 0; h < 2; h++) {
            int rl = wm * 32 + mf * 16 + h * 8 + gid;
            float v[8];
            float amax = 0.f;
#pragma unroll
            for (int nf = 0; nf < 4; nf++) {
                float2 p = upk2(acc2[mf][nf][h]);
                float v0 = p.x + sBias[wn * 32 + nf * 8 + tig * 2];
                float v1 = p.y + sBias[wn * 32 + nf * 8 + tig * 2 + 1];
                v[nf * 2 + 0] = v0;
                v[nf * 2 + 1] = v1;
                amax = fmaxf(amax, fmaxf(fabsf(v0), fabsf(v1)));
            }
            amax = fmaxf(amax, __shfl_xor_sync(0xffffffffu, amax, 1));
            amax = fmaxf(amax, __shfl_xor_sync(0xffffffffu, amax, 2));
            float scale = jax_scale(amax);
            float* orow = out + (size_t)(m0 + rl) * N_DIM + n0 + wn * 32;
#pragma unroll
            for (int nf = 0; nf < 4; nf++) {
                float2 qv;
#pragma unroll
                for (int j = 0; j < 2; j++) {
                    float t = v[nf * 2 + j] / scale;
                    float av = fabsf(t);
                    float r = 0.f;
                    if (av > 0.f) {
                        float sat = fminf(av, 57344.f);
                        int e = jax_floor_log2(sat);
                        e = e < -14 ? -14 : e;
                        float step = sStep[e + 14];
                        float q = rintf(sat / step) * step;   // literal ref math
                        r = copysignf(q, t) * scale;
                    }
                    (j == 0 ? qv.x : qv.y) = r;
                }
                *reinterpret_cast<float2*>(orow + nf * 8 + tig * 2) = qv;
            }
        }
    }
}

extern "C" void kernel_launch(void* const* d_in, const int* in_sizes, int n_in,
                              void* d_out, int out_size) {
    const float* x = (const float*)d_in[0];
    const float* w = (const float*)d_in[1];
    const float* bias = (const float*)d_in[2];
    float* out = (float*)d_out;

    int Mtot = in_sizes[0] / K_DIM;   // 65536
    int nbx = in_sizes[0] / 32;
    int nbw = in_sizes[1] / 32;

    void *pxv = nullptr, *pwv = nullptr, *pxs = nullptr, *pws = nullptr;
    cudaGetSymbolAddress(&pxv, g_xv);
    cudaGetSymbolAddress(&pwv, g_wv);
    cudaGetSymbolAddress(&pxs, g_xs);
    cudaGetSymbolAddress(&pws, g_ws);

    quant_v<<<(nbx + 255) / 256, 256>>>(x, (uint8_t*)pxv, (float*)pxs, nbx, Mtot);
    quant_v<<<(nbw + 255) / 256, 256>>>(w, (uint8_t*)pwv, (float*)pws, nbw, N_DIM);

    const int dyn_smem = NSTG * STG_BYTES * 2;   // 61440 bytes
    cudaFuncSetAttribute(gemm_qd, cudaFuncAttributeMaxDynamicSharedMemorySize, dyn_smem);
    dim3 grid(N_DIM / BN, Mtot / BM);
    gemm_qd<<<grid, 512, dyn_smem>>>(bias, out, Mtot);
}

// round 12
// speedup vs baseline: 1.0169x; 1.0169x over previous
#include <cuda_runtime.h>
#include <cuda_fp8.h>
#include <cstdint>
#include <cstddef>

#define K_DIM 1024
#define N_DIM 1024
#define NKB 32
#define LN2F 0.69314718246459960938f

#define BM 128
#define BN 128
#define BK 32                 // bytes per k-block (fp8) == one MX block
#define RSTRIDE 48            // bytes per smem row (32 data + 16 pad)
#define STG_BYTES (BM * RSTRIDE)
#define NSTG 5                // pipeline stages (prefetch distance 4)

// Exact e5m2 grid values stored AS fp8 + per-32-block scales (fp32, inexact jax)
__device__ __align__(16) uint8_t g_xv[(size_t)8 * 8192 * 1024];
__device__ __align__(16) uint8_t g_wv[(size_t)1024 * 1024];
__device__ __align__(16) float g_xs[(size_t)NKB * 65536];   // [kb][row]
__device__ __align__(16) float g_ws[(size_t)NKB * 1024];    // [kb][row]

// Rare path outlined: keeps ~35 instr of libdevice logf out of the hot loops'
// I$ footprint (64+ call sites previously inlined it).
__device__ __noinline__ int slow_floor_log2(float s) {
    return (int)floorf(logf(s) / LN2F);
}

// floor(logf(s)/ln2f) with exponent-bits fast path (bitwise-equal in fast region)
__device__ __forceinline__ int jax_floor_log2(float s) {
    uint32_t b = __float_as_uint(s);
    uint32_t mant = b & 0x7fffffu;
    int ef = (int)(b >> 23);
    if (ef == 0 || mant >= 0x7ff000u || (mant != 0u && mant <= 0x4000u))
        return slow_floor_log2(s);
    return ef - 127;
}

// Literal jax block scale: expf((floor(log2(amax)) - 15) * ln2f)
__device__ __forceinline__ float jax_scale(float amax) {
    if (!(amax > 0.f)) return 1.f;
    int E = jax_floor_log2(amax);
    return expf((float)(E - 15) * LN2F);
}

// One thread = one 32-element MX block. Emits exact e5m2 grid values (fp8) + scale.
__global__ __launch_bounds__(256) void quant_v(const float* __restrict__ x,
                                               uint8_t* __restrict__ qv,
                                               float* __restrict__ qs,
                                               int nblk, int rows) {
    __shared__ float sStep[30];
    if (threadIdx.x < 30) sStep[threadIdx.x] = expf((float)((int)threadIdx.x - 16) * LN2F);
    __syncthreads();
    int b = blockIdx.x * blockDim.x + threadIdx.x;
    if (b >= nblk) return;
    const float4* p = reinterpret_cast<const float4*>(x) + (size_t)b * 8;
    float4 v[8];
    float amax = 0.f;
#pragma unroll
    for (int i = 0; i < 8; i++) {
        v[i] = p[i];
        amax = fmaxf(amax, fmaxf(fmaxf(fabsf(v[i].x), fabsf(v[i].y)),
                                 fmaxf(fabsf(v[i].z), fabsf(v[i].w))));
    }
    float scale = jax_scale(amax);
    const float* f = reinterpret_cast<const float*>(v);
    uint4 ov[2];                                   // 32 fp8 bytes
    uint8_t* o = reinterpret_cast<uint8_t*>(ov);
#pragma unroll
    for (int i = 0; i < 32; i++) {
        float t = f[i] / scale;            // true div: selection bitwise as ref
        uint32_t tb = __float_as_uint(t);
        float av = __uint_as_float(tb & 0x7fffffffu);
        float r = 0.f;
        if (av > 0.f) {
            float sat = fminf(av, 57344.f);
            int e = jax_floor_log2(sat);
            e = e < -14 ? -14 : e;
            float step = sStep[e + 14];    // bitwise == expf((e-2)*ln2f)
            float n = rintf(sat / step);   // true div: bitwise as ref
            // ldexpf(n, e-2) == n * 2^(e-2); e-2 in [-16,13] -> normal pow2,
            // n has <=4-bit mantissa -> product exact (bitwise == ldexpf).
            float p2 = __uint_as_float((uint32_t)(e + 125) << 23);
            float mag = n * p2;
            r = __uint_as_float(__float_as_uint(mag) | (tb & 0x80000000u));
        }
        o[i] = __nv_cvt_float_to_fp8(r, __NV_SATFINITE, __NV_E5M2);  // exact
    }
    uint4* dst = reinterpret_cast<uint4*>(qv) + (size_t)b * 2;
    dst[0] = ov[0];
    dst[1] = ov[1];
    qs[(size_t)(b & 31) * rows + (b >> 5)] = scale;
}

__device__ __forceinline__ void cp_async16(uint32_t dst, const void* src) {
    asm volatile("cp.async.cg.shared.global [%0], [%1], 16;\n" :: "r"(dst), "l"(src));
}

__device__ __forceinline__ unsigned long long pk2(float lo, float hi) {
    unsigned long long r;
    asm("mov.b64 %0, {%1, %2};" : "=l"(r) : "f"(lo), "f"(hi));
    return r;
}
__device__ __forceinline__ float2 upk2(unsigned long long v) {
    float2 r;
    asm("mov.b64 {%0, %1}, %2;" : "=f"(r.x), "=f"(r.y) : "l"(v));
    return r;
}
__device__ __forceinline__ unsigned long long mul2(unsigned long long a,
                                                   unsigned long long b) {
    unsigned long long r;
    asm("mul.rn.f32x2 %0, %1, %2;" : "=l"(r) : "l"(a), "l"(b));
    return r;
}
__device__ __forceinline__ void fma2(unsigned long long& acc, unsigned long long a,
                                     unsigned long long b) {
    asm("fma.rn.f32x2 %0, %1, %2, %0;" : "+l"(acc) : "l"(a), "l"(b));
}

// 128x128 tile GEMM, 16 warps (warp tile 32x32), 5-stage cp.async pipeline,
// fp8-e5m2 m16n8k32 MMA (one per MX block) with immediate packed-f32x2 scale
// fold; literal jax out-quant in epilogue. (Mainloop is at the legacy-HMMA
// fallback rate floor on this toolchain target; left unchanged.)
__global__ __launch_bounds__(512) void gemm_qd(const float* __restrict__ bias,
                                               float* __restrict__ out, int mrows) {
    extern __shared__ uint8_t dynsm[];
    uint8_t* sA = dynsm;                       // [NSTG][STG_BYTES]
    uint8_t* sB = dynsm + NSTG * STG_BYTES;    // [NSTG][STG_BYTES]
    __shared__ float sSX[NSTG][BM];
    __shared__ float sSW[NSTG][BN];
    __shared__ float sBias[BN];
    __shared__ float sStep[30];

    const int tid = threadIdx.x;
    const int m0 = blockIdx.y * BM;
    const int n0 = blockIdx.x * BN;
    if (tid < 30) sStep[tid] = expf((float)(tid - 16) * LN2F);
    if (tid < BN) sBias[tid] = bias[n0 + tid];

    const int lane = tid & 31;
    const int warp = tid >> 5;          // 0..15
    const int wm = warp >> 2;           // 0..3  (32 rows)
    const int wn = warp & 3;            // 0..3  (32 cols = one quant block)

    uint32_t sAu[NSTG], sBu[NSTG], sSXu[NSTG], sSWu[NSTG];
#pragma unroll
    for (int s = 0; s < NSTG; s++) {
        sAu[s] = (uint32_t)__cvta_generic_to_shared(sA + s * STG_BYTES);
        sBu[s] = (uint32_t)__cvta_generic_to_shared(sB + s * STG_BYTES);
        sSXu[s] = (uint32_t)__cvta_generic_to_shared(&sSX[s][0]);
        sSWu[s] = (uint32_t)__cvta_generic_to_shared(&sSW[s][0]);
    }

    unsigned long long acc2[2][4][2];
#pragma unroll
    for (int i = 0; i < 2; i++)
#pragma unroll
        for (int j = 0; j < 4; j++)
#pragma unroll
            for (int h = 0; h < 2; h++) acc2[i][j][h] = 0ull;

    // 512 threads: tid<256 loads one 16B chunk of A, tid>=256 one of B.
    const int lrow = (tid & 255) >> 1, lch = tid & 1;
    auto load_stage = [&](int stage, int kt) {
        int k0 = kt * BK;
        if (tid < 256)
            cp_async16(sAu[stage] + (uint32_t)(lrow * RSTRIDE + lch * 16),
                       &g_xv[(size_t)(m0 + lrow) * K_DIM + k0 + lch * 16]);
        else
            cp_async16(sBu[stage] + (uint32_t)(lrow * RSTRIDE + lch * 16),
                       &g_wv[(size_t)(n0 + lrow) * K_DIM + k0 + lch * 16]);
        if (tid < 32)
            cp_async16(sSXu[stage] + tid * 16, &g_xs[(size_t)kt * mrows + m0 + tid * 4]);
        else if (tid < 64)
            cp_async16(sSWu[stage] + (tid - 32) * 16,
                       &g_ws[(size_t)kt * N_DIM + n0 + (tid - 32) * 4]);
        asm volatile("cp.async.commit_group;\n");
    };

    const int gid = lane >> 2, tig = lane & 3;
    const int NK = K_DIM / BK;   // 32

#pragma unroll
    for (int s = 0; s < 4; s++) load_stage(s, s);   // prefetch distance 4

    int st = 0;
    for (int kt = 0; kt < NK; kt++) {
        if (kt < NK - 3)      asm volatile("cp.async.wait_group 3;\n");
        else if (kt == NK - 3) asm volatile("cp.async.wait_group 2;\n");
        else if (kt == NK - 2) asm volatile("cp.async.wait_group 1;\n");
        else                   asm volatile("cp.async.wait_group 0;\n");
        __syncthreads();

        if (kt + 4 < NK) {
            int pf = st + 4 >= NSTG ? st - 1 : st + 4;
            load_stage(pf, kt + 4);
        }

        unsigned long long sxp[2][2], swp[4];
#pragma unroll
        for (int mf = 0; mf < 2; mf++) {
            float s0 = sSX[st][wm * 32 + mf * 16 + gid];
            float s1 = sSX[st][wm * 32 + mf * 16 + 8 + gid];
            sxp[mf][0] = pk2(s0, s0);
            sxp[mf][1] = pk2(s1, s1);
        }
#pragma unroll
        for (int nf = 0; nf < 4; nf++)
            swp[nf] = pk2(sSW[st][wn * 32 + nf * 8 + tig * 2],
                          sSW[st][wn * 32 + nf * 8 + tig * 2 + 1]);

        uint32_t a[2][4];
#pragma unroll
        for (int mf = 0; mf < 2; mf++) {
            uint32_t addr = sAu[st] +
                (uint32_t)((wm * 32 + mf * 16 + (lane & 15)) * RSTRIDE +
                           (lane >> 4) * 16);
            asm volatile("ldmatrix.sync.aligned.m8n8.x4.shared.b16 {%0,%1,%2,%3}, [%4];\n"
                         : "=r"(a[mf][0]), "=r"(a[mf][1]), "=r"(a[mf][2]), "=r"(a[mf][3])
                         : "r"(addr));
        }
        uint32_t b[4][2];
#pragma unroll
        for (int np = 0; np < 2; np++) {
            uint32_t addr = sBu[st] +
                (uint32_t)((wn * 32 + np * 16 + ((lane >> 4) & 1) * 8 + (lane & 7)) * RSTRIDE +
                           ((lane >> 3) & 1) * 16);
            asm volatile("ldmatrix.sync.aligned.m8n8.x4.shared.b16 {%0,%1,%2,%3}, [%4];\n"
                         : "=r"(b[np * 2][0]), "=r"(b[np * 2][1]),
                           "=r"(b[np * 2 + 1][0]), "=r"(b[np * 2 + 1][1])
                         : "r"(addr));
        }

#pragma unroll
        for (int mf = 0; mf < 2; mf++)
#pragma unroll
            for (int nf = 0; nf < 4; nf++) {
                float c0 = 0.f, c1 = 0.f, c2 = 0.f, c3 = 0.f;
                asm volatile(
                    "mma.sync.aligned.m16n8k32.row.col.f32.e5m2.e5m2.f32 "
                    "{%0,%1,%2,%3}, {%4,%5,%6,%7}, {%8,%9}, {%0,%1,%2,%3};\n"
                    : "+f"(c0), "+f"(c1), "+f"(c2), "+f"(c3)
                    : "r"(a[mf][0]), "r"(a[mf][1]), "r"(a[mf][2]), "r"(a[mf][3]),
                      "r"(b[nf][0]), "r"(b[nf][1]));
                fma2(acc2[mf][nf][0], pk2(c0, c1), mul2(sxp[mf][0], swp[nf]));
                fma2(acc2[mf][nf][1], pk2(c2, c3), mul2(sxp[mf][1], swp[nf]));
            }

        st = st + 1 >= NSTG ? 0 : st + 1;
    }

    // Epilogue: +bias, literal jax MX e5m2 quant-dequant over 32 consecutive n.
#pragma unroll
    for (int mf = 0; mf < 2; mf++) {
#pragma unroll
        for (int h = 0; h < 2; h++) {
            int rl = wm * 32 + mf * 16 + h * 8 + gid;
            float v[8];
            float amax = 0.f;
#pragma unroll
            for (int nf = 0; nf < 4; nf++) {
                float2 p = upk2(acc2[mf][nf][h]);
                float v0 = p.x + sBias[wn * 32 + nf * 8 + tig * 2];
                float v1 = p.y + sBias[wn * 32 + nf * 8 + tig * 2 + 1];
                v[nf * 2 + 0] = v0;
                v[nf * 2 + 1] = v1;
                amax = fmaxf(amax, fmaxf(fabsf(v0), fabsf(v1)));
            }
            amax = fmaxf(amax, __shfl_xor_sync(0xffffffffu, amax, 1));
            amax = fmaxf(amax, __shfl_xor_sync(0xffffffffu, amax, 2));
            float scale = jax_scale(amax);
            float* orow = out + (size_t)(m0 + rl) * N_DIM + n0 + wn * 32;
#pragma unroll
            for (int nf = 0; nf < 4; nf++) {
                float2 qv;
#pragma unroll
                for (int j = 0; j < 2; j++) {
                    float t = v[nf * 2 + j] / scale;
                    uint32_t tb = __float_as_uint(t);
                    float av = __uint_as_float(tb & 0x7fffffffu);
                    float r = 0.f;
                    if (av > 0.f) {
                        float sat = fminf(av, 57344.f);
                        int e = jax_floor_log2(sat);
                        e = e < -14 ? -14 : e;
                        float step = sStep[e + 14];
                        float q = rintf(sat / step) * step;   // literal ref math
                        r = __uint_as_float(__float_as_uint(q) | (tb & 0x80000000u)) * scale;
                    }
                    (j == 0 ? qv.x : qv.y) = r;
                }
                *reinterpret_cast<float2*>(orow + nf * 8 + tig * 2) = qv;
            }
        }
    }
}

extern "C" void kernel_launch(void* const* d_in, const int* in_sizes, int n_in,
                              void* d_out, int out_size) {
    const float* x = (const float*)d_in[0];
    const float* w = (const float*)d_in[1];
    const float* bias = (const float*)d_in[2];
    float* out = (float*)d_out;

    int Mtot = in_sizes[0] / K_DIM;   // 65536
    int nbx = in_sizes[0] / 32;
    int nbw = in_sizes[1] / 32;

    void *pxv = nullptr, *pwv = nullptr, *pxs = nullptr, *pws = nullptr;
    cudaGetSymbolAddress(&pxv, g_xv);
    cudaGetSymbolAddress(&pwv, g_wv);
    cudaGetSymbolAddress(&pxs, g_xs);
    cudaGetSymbolAddress(&pws, g_ws);

    quant_v<<<(nbx + 255) / 256, 256>>>(x, (uint8_t*)pxv, (float*)pxs, nbx, Mtot);
    quant_v<<<(nbw + 255) / 256, 256>>>(w, (uint8_t*)pwv, (float*)pws, nbw, N_DIM);

    const int dyn_smem = NSTG * STG_BYTES * 2;   // 61440 bytes
    cudaFuncSetAttribute(gemm_qd, cudaFuncAttributeMaxDynamicSharedMemorySize, dyn_smem);
    dim3 grid(N_DIM / BN, Mtot / BM);
    gemm_qd<<<grid, 512, dyn_smem>>>(bias, out, Mtot);
}